// round 2
// baseline (speedup 1.0000x reference)
#include <cuda_runtime.h>
#include <math.h>
#include <stdint.h>
#include <stddef.h>

#define N_NODES 400000
#define N_EDGES 1600000
#define F_IN    100
#define EMB     128
#define GG      11
#define SORTK   64
#define DCAT    385
#define XC_STRIDE 388   // padded row stride for concat features (16B aligned)

// ------------------------- scratch (device globals) -------------------------
__device__ float g_h[(size_t)N_NODES * EMB];       // 205 MB
__device__ float g_agg[(size_t)N_NODES * EMB];     // 205 MB
__device__ float g_xc[(size_t)N_NODES * XC_STRIDE];// 621 MB  cols: 0-127 x1, 128-255 x2, 256-383 x3, 384 x4
__device__ float g_deg[N_NODES];
__device__ float g_dis[N_NODES];
__device__ float g_selfnorm[N_NODES];
__device__ float g_normw[N_EDGES];
__device__ float g_h4[N_NODES];
__device__ float g_agg4[N_NODES];
__device__ float g_score[N_NODES];
__device__ int   g_starts[GG + 1];
__device__ int   g_topidx[GG * SORTK];
__device__ float g_pooled[GG * SORTK * DCAT];
__device__ float g_h5[GG * 64 * 64];
__device__ float g_mp[GG * 64 * 32];
__device__ float g_h6[GG * 128 * 28];   // == flattened emb (39424)
__device__ float g_out1[128];

// ------------------------- degree / norm -------------------------
__global__ void k_init_deg() {
    int i = blockIdx.x * blockDim.x + threadIdx.x;
    if (i < N_NODES) g_deg[i] = 1.0f;
}

__global__ void k_deg_scatter(const int* __restrict__ src, const int* __restrict__ dst) {
    int e = blockIdx.x * blockDim.x + threadIdx.x;
    if (e >= N_EDGES) return;
    int s = src[e], d = dst[e];
    if (s != d) atomicAdd(&g_deg[d], 1.0f);
}

__global__ void k_disnorm() {
    int i = blockIdx.x * blockDim.x + threadIdx.x;
    if (i >= N_NODES) return;
    float dis = rsqrtf(g_deg[i]);
    g_dis[i] = dis;
    g_selfnorm[i] = dis * dis;
}

__global__ void k_edge_norm(const int* __restrict__ src, const int* __restrict__ dst) {
    int e = blockIdx.x * blockDim.x + threadIdx.x;
    if (e >= N_EDGES) return;
    int s = src[e], d = dst[e];
    g_normw[e] = (s != d) ? g_dis[s] * g_dis[d] : 0.0f;
}

// ------------------------- GCN GEMM: H = X @ W ; AGG = H*self_norm + b -----
// tile 128 rows x 128 cols, 256 threads, 8x8 microtile, KC=16
#define KC 16
__global__ __launch_bounds__(256) void k_gcn_gemm(
    const float* __restrict__ Xext, int xcColOff, int ldx, int K,
    const float* __restrict__ W, const float* __restrict__ bias)
{
    __shared__ float Xs[KC][132];
    __shared__ float Ws[KC][128];

    int tid = threadIdx.x;
    int tx = tid & 15;          // col group (8 cols)
    int ty = tid >> 4;          // row group (8 rows)
    int rowBase = blockIdx.x * 128;

    const float* Xbase = (xcColOff < 0) ? Xext : (g_xc + xcColOff);

    float acc[8][8];
#pragma unroll
    for (int i = 0; i < 8; ++i)
#pragma unroll
        for (int j = 0; j < 8; ++j) acc[i][j] = 0.0f;

    int nChunks = (K + KC - 1) / KC;
    for (int c = 0; c < nChunks; ++c) {
        int k0 = c * KC;
        // stage X chunk: rows rowBase..+127, k = k0..k0+15 ; thread: row=tid>>1, half=(tid&1)*8
        {
            int r = tid >> 1;
            int kh = (tid & 1) * 8;
            int grow = rowBase + r;   // rowBase+127 < 400000 always (400000 = 3125*128)
            const float* xr = Xbase + (size_t)grow * ldx;
#pragma unroll
            for (int j = 0; j < 8; ++j) {
                int kk = k0 + kh + j;
                float v = (kk < K) ? xr[kk] : 0.0f;
                Xs[kh + j][r] = v;
            }
        }
        // stage W chunk: k rows k0..+15, 128 cols ; thread: kw=tid>>4, cw=(tid&15)*8
        {
            int kw = tid >> 4;
            int cw = (tid & 15) * 8;
            if (k0 + kw < K) {
                const float* wr = W + (size_t)(k0 + kw) * 128 + cw;
                float4 v0 = *(const float4*)(wr);
                float4 v1 = *(const float4*)(wr + 4);
                *(float4*)&Ws[kw][cw] = v0;
                *(float4*)&Ws[kw][cw + 4] = v1;
            } else {
                float4 z = make_float4(0.f, 0.f, 0.f, 0.f);
                *(float4*)&Ws[kw][cw] = z;
                *(float4*)&Ws[kw][cw + 4] = z;
            }
        }
        __syncthreads();
#pragma unroll
        for (int k = 0; k < KC; ++k) {
            float a[8], b[8];
            *(float4*)&a[0] = *(const float4*)&Xs[k][ty * 8];
            *(float4*)&a[4] = *(const float4*)&Xs[k][ty * 8 + 4];
            *(float4*)&b[0] = *(const float4*)&Ws[k][tx * 8];
            *(float4*)&b[4] = *(const float4*)&Ws[k][tx * 8 + 4];
#pragma unroll
            for (int i = 0; i < 8; ++i)
#pragma unroll
                for (int j = 0; j < 8; ++j)
                    acc[i][j] = fmaf(a[i], b[j], acc[i][j]);
        }
        __syncthreads();
    }

    // epilogue: H = acc ; AGG = acc*self_norm + bias
    float bj[8];
#pragma unroll
    for (int j = 0; j < 8; ++j) bj[j] = bias[tx * 8 + j];
#pragma unroll
    for (int i = 0; i < 8; ++i) {
        int row = rowBase + ty * 8 + i;
        float sn = g_selfnorm[row];
        size_t base = (size_t)row * 128 + tx * 8;
        float4 h0, h1, a0, a1;
        h0.x = acc[i][0]; h0.y = acc[i][1]; h0.z = acc[i][2]; h0.w = acc[i][3];
        h1.x = acc[i][4]; h1.y = acc[i][5]; h1.z = acc[i][6]; h1.w = acc[i][7];
        a0.x = fmaf(acc[i][0], sn, bj[0]); a0.y = fmaf(acc[i][1], sn, bj[1]);
        a0.z = fmaf(acc[i][2], sn, bj[2]); a0.w = fmaf(acc[i][3], sn, bj[3]);
        a1.x = fmaf(acc[i][4], sn, bj[4]); a1.y = fmaf(acc[i][5], sn, bj[5]);
        a1.z = fmaf(acc[i][6], sn, bj[6]); a1.w = fmaf(acc[i][7], sn, bj[7]);
        *(float4*)&g_h[base]     = h0;
        *(float4*)&g_h[base + 4] = h1;
        *(float4*)&g_agg[base]     = a0;
        *(float4*)&g_agg[base + 4] = a1;
    }
}

// ------------------------- edge scatter (warp per edge, 4 cols/lane) --------
__global__ void k_scatter(const int* __restrict__ src, const int* __restrict__ dst) {
    int warp = (blockIdx.x * blockDim.x + threadIdx.x) >> 5;
    int lane = threadIdx.x & 31;
    if (warp >= N_EDGES) return;
    float w = g_normw[warp];
    if (w == 0.0f) return;
    int s = src[warp], d = dst[warp];
    float4 v = *(const float4*)(g_h + (size_t)s * 128 + lane * 4);
    float* ap = g_agg + (size_t)d * 128 + lane * 4;
    atomicAdd(ap + 0, v.x * w);
    atomicAdd(ap + 1, v.y * w);
    atomicAdd(ap + 2, v.z * w);
    atomicAdd(ap + 3, v.w * w);
}

// ------------------------- tanh -> xc column block --------------------------
__global__ void k_tanh_big(int colOff) {
    int i = blockIdx.x * blockDim.x + threadIdx.x;   // over N*32 float4s
    if (i >= N_NODES * 32) return;
    int node = i >> 5;
    int c4 = (i & 31);
    float4 v = ((const float4*)g_agg)[i];
    v.x = tanhf(v.x); v.y = tanhf(v.y); v.z = tanhf(v.z); v.w = tanhf(v.w);
    *(float4*)&g_xc[(size_t)node * XC_STRIDE + colOff + c4 * 4] = v;
}

// ------------------------- layer 4 (EMB -> 1) -------------------------------
__global__ void k_layer4_dot(const float* __restrict__ W4, const float* __restrict__ b4) {
    int warp = (blockIdx.x * blockDim.x + threadIdx.x) >> 5;
    int lane = threadIdx.x & 31;
    if (warp >= N_NODES) return;
    const float* xr = g_xc + (size_t)warp * XC_STRIDE + 256;
    float4 v = *(const float4*)(xr + lane * 4);
    float4 w = *(const float4*)(W4 + lane * 4);
    float p = v.x * w.x + v.y * w.y + v.z * w.z + v.w * w.w;
#pragma unroll
    for (int off = 16; off; off >>= 1) p += __shfl_down_sync(0xffffffffu, p, off);
    if (lane == 0) {
        g_h4[warp] = p;
        g_agg4[warp] = fmaf(p, g_selfnorm[warp], b4[0]);
    }
}

__global__ void k_scatter4(const int* __restrict__ src, const int* __restrict__ dst) {
    int e = blockIdx.x * blockDim.x + threadIdx.x;
    if (e >= N_EDGES) return;
    float w = g_normw[e];
    if (w == 0.0f) return;
    atomicAdd(&g_agg4[dst[e]], w * g_h4[src[e]]);
}

__global__ void k_tanh4() {
    int i = blockIdx.x * blockDim.x + threadIdx.x;
    if (i >= N_NODES) return;
    float t = tanhf(g_agg4[i]);
    g_xc[(size_t)i * XC_STRIDE + 384] = t;
    g_score[i] = t;
}

// ------------------------- graph bounds -------------------------------------
__global__ void k_bounds(const int* __restrict__ batch) {
    int g = threadIdx.x;
    if (g > GG) return;
    if (g == GG) { g_starts[GG] = N_NODES; return; }
    int lo = 0, hi = N_NODES;
    while (lo < hi) {
        int mid = (lo + hi) >> 1;
        if (batch[mid] < g) lo = mid + 1; else hi = mid;
    }
    g_starts[g] = lo;
}

// ------------------------- top-64 per graph (iterative argmax) --------------
__global__ __launch_bounds__(1024) void k_topk() {
    int g = blockIdx.x;
    int s = g_starts[g], e = g_starts[g + 1];
    int tid = threadIdx.x;
    __shared__ float sv[32];
    __shared__ int   si[32];

    for (int k = 0; k < SORTK; ++k) {
        float best = -1e30f;
        int bi = -1;
        for (int i = s + tid; i < e; i += 1024) {
            float v = g_score[i];
            if (v > -1e9f && (v > best || (v == best && i < bi))) { best = v; bi = i; }
        }
        // warp reduce
#pragma unroll
        for (int off = 16; off; off >>= 1) {
            float ov = __shfl_down_sync(0xffffffffu, best, off);
            int   oi = __shfl_down_sync(0xffffffffu, bi, off);
            bool take = (oi != -1) && (bi == -1 || ov > best || (ov == best && oi < bi));
            if (take) { best = ov; bi = oi; }
        }
        int lane = tid & 31, wid = tid >> 5;
        if (lane == 0) { sv[wid] = best; si[wid] = bi; }
        __syncthreads();
        if (wid == 0) {
            best = sv[lane]; bi = si[lane];
#pragma unroll
            for (int off = 16; off; off >>= 1) {
                float ov = __shfl_down_sync(0xffffffffu, best, off);
                int   oi = __shfl_down_sync(0xffffffffu, bi, off);
                bool take = (oi != -1) && (bi == -1 || ov > best || (ov == best && oi < bi));
                if (take) { best = ov; bi = oi; }
            }
            if (lane == 0) {
                g_topidx[g * SORTK + k] = bi;
                if (bi >= 0) g_score[bi] = -1e30f;   // exclude
            }
        }
        __syncthreads();
    }
}

// ------------------------- pooled gather ------------------------------------
__global__ void k_pool_gather() {
    int gt = blockIdx.x;              // 0..703
    int idx = g_topidx[gt];
    float* outp = g_pooled + (size_t)gt * DCAT;
    if (idx >= 0) {
        const float* inp = g_xc + (size_t)idx * XC_STRIDE;
        for (int c = threadIdx.x; c < DCAT; c += blockDim.x) outp[c] = inp[c];
    } else {
        for (int c = threadIdx.x; c < DCAT; c += blockDim.x) outp[c] = 0.0f;
    }
}

// ------------------------- conv5 (stride-385 conv == per-row GEMV) ----------
__global__ void k_conv5(const float* __restrict__ cw5, const float* __restrict__ cb5) {
    int gt = blockIdx.x;              // 0..703 : g = gt>>6, t = gt&63
    int g = gt >> 6, t = gt & 63;
    __shared__ float row[DCAT];
    const float* pr = g_pooled + (size_t)gt * DCAT;
    for (int c = threadIdx.x; c < DCAT; c += 64) row[c] = pr[c];
    __syncthreads();
    int oc = threadIdx.x;             // 64 threads
    float acc = cb5[oc];
    const float* w = cw5 + oc * DCAT;
    for (int j = 0; j < DCAT; ++j) acc = fmaf(w[j], row[j], acc);
    g_h5[(g * 64 + oc) * 64 + t] = fmaxf(acc, 0.0f);
}

// ------------------------- maxpool ------------------------------------------
__global__ void k_maxpool() {
    int i = blockIdx.x * blockDim.x + threadIdx.x;
    if (i >= GG * 64 * 32) return;
    g_mp[i] = fmaxf(g_h5[2 * i], g_h5[2 * i + 1]);
}

// ------------------------- conv6 --------------------------------------------
__global__ void k_conv6(const float* __restrict__ cw6, const float* __restrict__ cb6) {
    int g = blockIdx.x;               // 0..10
    int oc = threadIdx.x;             // 128 threads
    __shared__ float sm[64 * 32];
    for (int i = oc; i < 64 * 32; i += 128) sm[i] = g_mp[g * 64 * 32 + i];
    __syncthreads();
    float acc[28];
    float cb = cb6[oc];
#pragma unroll
    for (int t = 0; t < 28; ++t) acc[t] = cb;
    for (int ic = 0; ic < 64; ++ic) {
#pragma unroll
        for (int kk = 0; kk < 5; ++kk) {
            float w = cw6[(oc * 64 + ic) * 5 + kk];
            const float* srow = &sm[ic * 32 + kk];
#pragma unroll
            for (int t = 0; t < 28; ++t) acc[t] = fmaf(w, srow[t], acc[t]);
        }
    }
    float* outp = g_h6 + g * 3584 + oc * 28;
#pragma unroll
    for (int t = 0; t < 28; ++t) outp[t] = fmaxf(acc[t], 0.0f);
}

// ------------------------- dense layers -------------------------------------
__inline__ __device__ float blockReduceSum(float v) {
    __shared__ float sh[32];
    int lane = threadIdx.x & 31, wid = threadIdx.x >> 5;
#pragma unroll
    for (int o = 16; o; o >>= 1) v += __shfl_down_sync(0xffffffffu, v, o);
    if (lane == 0) sh[wid] = v;
    __syncthreads();
    v = (threadIdx.x < (blockDim.x >> 5)) ? sh[lane] : 0.0f;
    if (wid == 0)
#pragma unroll
        for (int o = 16; o; o >>= 1) v += __shfl_down_sync(0xffffffffu, v, o);
    return v;
}

__global__ void k_dense1(const float* __restrict__ fw1, const float* __restrict__ fb1) {
    int j = blockIdx.x;               // 0..127
    const float* w = fw1 + (size_t)j * (GG * 3584);
    float s = 0.0f;
    for (int i = threadIdx.x; i < GG * 3584; i += blockDim.x) s = fmaf(g_h6[i], w[i], s);
    s = blockReduceSum(s);
    if (threadIdx.x == 0) g_out1[j] = fmaxf(s + fb1[j], 0.0f);
}

__global__ void k_dense2(const float* __restrict__ fw2, const float* __restrict__ fb2,
                         float* __restrict__ out) {
    __shared__ float so[128];
    int tid = threadIdx.x;            // 128 threads
    so[tid] = g_out1[tid];
    __syncthreads();
    if (tid < 10) {
        float s = fb2[tid];
        const float* w = fw2 + tid * 128;
        for (int j = 0; j < 128; ++j) s = fmaf(w[j], so[j], s);
        out[tid] = s;
    }
}

// ------------------------- launch -------------------------------------------
extern "C" void kernel_launch(void* const* d_in, const int* in_sizes, int n_in,
                              void* d_out, int out_size) {
    const float* x     = (const float*)d_in[0];
    const int*   ei    = (const int*)d_in[1];
    const int*   batch = (const int*)d_in[2];
    const float* W1 = (const float*)d_in[3];  const float* b1 = (const float*)d_in[4];
    const float* W2 = (const float*)d_in[5];  const float* b2 = (const float*)d_in[6];
    const float* W3 = (const float*)d_in[7];  const float* b3 = (const float*)d_in[8];
    const float* W4 = (const float*)d_in[9];  const float* b4 = (const float*)d_in[10];
    const float* cw5 = (const float*)d_in[11]; const float* cb5 = (const float*)d_in[12];
    const float* cw6 = (const float*)d_in[13]; const float* cb6 = (const float*)d_in[14];
    const float* fw1 = (const float*)d_in[15]; const float* fb1 = (const float*)d_in[16];
    const float* fw2 = (const float*)d_in[17]; const float* fb2 = (const float*)d_in[18];
    float* out = (float*)d_out;

    const int* src = ei;
    const int* dst = ei + N_EDGES;

    const int NB_N = (N_NODES + 255) / 256;      // 1563
    const int NB_E = (N_EDGES + 255) / 256;      // 6250
    const int NB_GEMM = N_NODES / 128;           // 3125
    const int NB_SCAT = (N_EDGES * 32 + 255) / 256;  // 200000
    const int NB_TANH = (N_NODES * 32 + 255) / 256;  // 50000
    const int NB_DOT4 = (N_NODES * 32 + 255) / 256;  // 50000

    // degrees / norms
    k_init_deg<<<NB_N, 256>>>();
    k_deg_scatter<<<NB_E, 256>>>(src, dst);
    k_disnorm<<<NB_N, 256>>>();
    k_edge_norm<<<NB_E, 256>>>(src, dst);

    // layer 1 (K = 100, external X)
    k_gcn_gemm<<<NB_GEMM, 256>>>(x, -1, F_IN, F_IN, W1, b1);
    k_scatter<<<NB_SCAT, 256>>>(src, dst);
    k_tanh_big<<<NB_TANH, 256>>>(0);

    // layer 2 (K = 128, X = xc cols 0..127)
    k_gcn_gemm<<<NB_GEMM, 256>>>(nullptr, 0, XC_STRIDE, EMB, W2, b2);
    k_scatter<<<NB_SCAT, 256>>>(src, dst);
    k_tanh_big<<<NB_TANH, 256>>>(128);

    // layer 3 (K = 128, X = xc cols 128..255)
    k_gcn_gemm<<<NB_GEMM, 256>>>(nullptr, 128, XC_STRIDE, EMB, W3, b3);
    k_scatter<<<NB_SCAT, 256>>>(src, dst);
    k_tanh_big<<<NB_TANH, 256>>>(256);

    // layer 4 (EMB -> 1)
    k_layer4_dot<<<NB_DOT4, 256>>>(W4, b4);
    k_scatter4<<<NB_E, 256>>>(src, dst);
    k_tanh4<<<NB_N, 256>>>();

    // sort pooling
    k_bounds<<<1, 32>>>(batch);
    k_topk<<<GG, 1024>>>();
    k_pool_gather<<<GG * SORTK, 128>>>();

    // conv head
    k_conv5<<<GG * SORTK, 64>>>(cw5, cb5);
    k_maxpool<<<(GG * 64 * 32 + 255) / 256, 256>>>();
    k_conv6<<<GG, 128>>>(cw6, cb6);

    // dense head
    k_dense1<<<128, 256>>>(fw1, fb1);
    k_dense2<<<1, 128>>>(fw2, fb2, out);
}

// round 6
// speedup vs baseline: 1.5130x; 1.5130x over previous
#include <cuda_runtime.h>
#include <math.h>
#include <stdint.h>
#include <stddef.h>

#define N_NODES 400000
#define N_EDGES 1600000
#define F_IN    100
#define EMB     128
#define GG      11
#define SORTK   64
#define DCAT    385
#define XC_STRIDE 388
#define SCAN_B  1024
#define NBLK_SCAN ((N_NODES + SCAN_B - 1) / SCAN_B)   // 391

typedef unsigned long long u64t;

// ------------------------- scratch (device globals) -------------------------
__device__ float g_h[(size_t)N_NODES * EMB];        // 205 MB
__device__ float g_xc[(size_t)N_NODES * XC_STRIDE]; // 621 MB
__device__ float g_dis[N_NODES];
__device__ float g_selfnorm[N_NODES];
__device__ int   g_cnt[N_NODES];
__device__ int   g_rowstart[N_NODES + 1];
__device__ int   g_cursor[N_NODES];
__device__ int   g_blk[NBLK_SCAN];
__device__ int   g_blkoff[NBLK_SCAN];
__device__ int   g_srcs[N_EDGES];
__device__ float g_ws[N_EDGES];
__device__ float g_h4[N_NODES];
__device__ float g_score[N_NODES];
__device__ int   g_starts[GG + 1];
__device__ int   g_topidx[GG * SORTK];
__device__ float g_pooled[GG * SORTK * DCAT];
__device__ float g_h5[GG * 64 * 64];
__device__ float g_mp[GG * 64 * 32];
__device__ float g_h6[GG * 128 * 28];
__device__ float g_out1[128];

// ------------------------- CSR build ----------------------------------------
__global__ void k_zero() {
    int i = blockIdx.x * blockDim.x + threadIdx.x;
    if (i < N_NODES) { g_cnt[i] = 0; g_cursor[i] = 0; }
}

__global__ void k_count(const int* __restrict__ src, const int* __restrict__ dst) {
    int e = blockIdx.x * blockDim.x + threadIdx.x;
    if (e >= N_EDGES) return;
    int s = src[e], d = dst[e];
    if (s != d) atomicAdd(&g_cnt[d], 1);
}

__global__ __launch_bounds__(SCAN_B) void k_scanA() {
    __shared__ int sm[SCAN_B];
    int t = threadIdx.x;
    int i = blockIdx.x * SCAN_B + t;
    int v = (i < N_NODES) ? g_cnt[i] : 0;
    sm[t] = v;
    __syncthreads();
#pragma unroll
    for (int off = 1; off < SCAN_B; off <<= 1) {
        int x = (t >= off) ? sm[t - off] : 0;
        __syncthreads();
        sm[t] += x;
        __syncthreads();
    }
    if (i < N_NODES) g_rowstart[i] = sm[t] - v;   // exclusive
    if (t == SCAN_B - 1) g_blk[blockIdx.x] = sm[t];
}

__global__ void k_scanB() {
    if (threadIdx.x == 0) {
        int run = 0;
        for (int b = 0; b < NBLK_SCAN; ++b) { g_blkoff[b] = run; run += g_blk[b]; }
        g_rowstart[N_NODES] = run;
    }
}

__global__ void k_scanC() {
    int i = blockIdx.x * blockDim.x + threadIdx.x;
    if (i < N_NODES) g_rowstart[i] += g_blkoff[blockIdx.x * blockDim.x / SCAN_B + (threadIdx.x >= SCAN_B ? 1 : 0)];
}
// (blockDim == SCAN_B so the above reduces to g_blkoff[blockIdx.x])

__global__ void k_disnorm() {
    int i = blockIdx.x * blockDim.x + threadIdx.x;
    if (i >= N_NODES) return;
    float deg = (float)g_cnt[i] + 1.0f;
    float dis = rsqrtf(deg);
    g_dis[i] = dis;
    g_selfnorm[i] = 1.0f / deg;
}

__global__ void k_place(const int* __restrict__ src, const int* __restrict__ dst) {
    int e = blockIdx.x * blockDim.x + threadIdx.x;
    if (e >= N_EDGES) return;
    int s = src[e], d = dst[e];
    if (s == d) return;
    int p = g_rowstart[d] + atomicAdd(&g_cursor[d], 1);
    g_srcs[p] = s;
    g_ws[p] = g_dis[s] * g_dis[d];
}

// ------------------------- GEMM: H = X @ W  (packed f32x2 FMA) --------------
#define KC 16
__device__ __forceinline__ u64t ffma2(u64t a, u64t b, u64t c) {
    u64t d;
    asm("fma.rn.f32x2 %0, %1, %2, %3;" : "=l"(d) : "l"(a), "l"(b), "l"(c));
    return d;
}
union F2U { u64t u; float2 f; };

__global__ __launch_bounds__(256) void k_gemm(
    const float* __restrict__ Xext, int xcColOff, int ldx, int K,
    const float* __restrict__ W)
{
    __shared__ float Xs[KC][132];
    __shared__ float Wd[KC][256];   // duplicated pairs, bit-swapped layout

    int tid = threadIdx.x;
    int tx = tid & 15;     // col group (8 cols)
    int ty = tid >> 4;     // row group (8 rows)
    int rowBase = blockIdx.x * 128;

    const float* Xbase = (xcColOff < 0) ? Xext : (g_xc + xcColOff);

    u64t acc2[4][8];
#pragma unroll
    for (int i = 0; i < 4; ++i)
#pragma unroll
        for (int j = 0; j < 8; ++j) acc2[i][j] = 0ull;

    int nChunks = (K + KC - 1) / KC;
    for (int c = 0; c < nChunks; ++c) {
        int k0 = c * KC;
        // stage X: rows rowBase..+127, k0..k0+15 ; thread: row = tid>>1, half=(tid&1)*8
        {
            int r = tid >> 1;
            int kh = (tid & 1) * 8;
            const float* xr = Xbase + (size_t)(rowBase + r) * ldx;
#pragma unroll
            for (int j = 0; j < 8; ++j) {
                int kk = k0 + kh + j;
                Xs[kh + j][r] = (kk < K) ? __ldg(xr + kk) : 0.0f;
            }
        }
        // stage W duplicated: col c -> float2 at word index (c&7)<<4 | c>>3
        {
            int kw = tid >> 4;
            int c0 = (tid & 15) * 8;
            if (k0 + kw < K) {
                const float* wr = W + (size_t)(k0 + kw) * 128 + c0;
#pragma unroll
                for (int j = 0; j < 8; ++j) {
                    float v = wr[j];
                    int cc = c0 + j;
                    int w = ((cc & 7) << 4) | (cc >> 3);
                    *(float2*)&Wd[kw][2 * w] = make_float2(v, v);
                }
            } else {
#pragma unroll
                for (int j = 0; j < 8; ++j) {
                    int cc = c0 + j;
                    int w = ((cc & 7) << 4) | (cc >> 3);
                    *(float2*)&Wd[kw][2 * w] = make_float2(0.f, 0.f);
                }
            }
        }
        __syncthreads();
#pragma unroll
        for (int k = 0; k < KC; ++k) {
            u64t a2[4], b2[8];
#pragma unroll
            for (int i = 0; i < 4; ++i)
                a2[i] = *(const u64t*)&Xs[k][ty * 8 + 2 * i];
#pragma unroll
            for (int j = 0; j < 8; ++j)
                b2[j] = *(const u64t*)&Wd[k][2 * ((j << 4) | tx)];
#pragma unroll
            for (int i = 0; i < 4; ++i)
#pragma unroll
                for (int j = 0; j < 8; ++j)
                    acc2[i][j] = ffma2(a2[i], b2[j], acc2[i][j]);
        }
        __syncthreads();
    }

    // epilogue: write H rows (pairs)
#pragma unroll
    for (int ip = 0; ip < 4; ++ip) {
        int row0 = rowBase + ty * 8 + 2 * ip;
        float4 lo0, lo1, hi0, hi1;
        F2U u;
        u.u = acc2[ip][0]; lo0.x = u.f.x; hi0.x = u.f.y;
        u.u = acc2[ip][1]; lo0.y = u.f.x; hi0.y = u.f.y;
        u.u = acc2[ip][2]; lo0.z = u.f.x; hi0.z = u.f.y;
        u.u = acc2[ip][3]; lo0.w = u.f.x; hi0.w = u.f.y;
        u.u = acc2[ip][4]; lo1.x = u.f.x; hi1.x = u.f.y;
        u.u = acc2[ip][5]; lo1.y = u.f.x; hi1.y = u.f.y;
        u.u = acc2[ip][6]; lo1.z = u.f.x; hi1.z = u.f.y;
        u.u = acc2[ip][7]; lo1.w = u.f.x; hi1.w = u.f.y;
        size_t b0 = (size_t)row0 * 128 + tx * 8;
        *(float4*)&g_h[b0]       = lo0;
        *(float4*)&g_h[b0 + 4]   = lo1;
        *(float4*)&g_h[b0 + 128] = hi0;
        *(float4*)&g_h[b0 + 132] = hi1;
    }
}

// ------------- fused aggregate + tanh -> xc (warp per node) -----------------
__global__ __launch_bounds__(256) void k_agg_tanh(int outOff, const float* __restrict__ bias) {
    int warp = (blockIdx.x * blockDim.x + threadIdx.x) >> 5;
    int lane = threadIdx.x & 31;
    if (warp >= N_NODES) return;
    int node = warp;

    float4 bj = *(const float4*)(bias + lane * 4);
    float sn = g_selfnorm[node];
    float4 hv = *(const float4*)(g_h + (size_t)node * 128 + lane * 4);
    float4 acc;
    acc.x = fmaf(hv.x, sn, bj.x);
    acc.y = fmaf(hv.y, sn, bj.y);
    acc.z = fmaf(hv.z, sn, bj.z);
    acc.w = fmaf(hv.w, sn, bj.w);

    int e0 = g_rowstart[node], e1 = g_rowstart[node + 1];
    for (int e = e0; e < e1; ++e) {
        int s = __ldg(&g_srcs[e]);
        float w = __ldg(&g_ws[e]);
        float4 v = __ldg((const float4*)(g_h + (size_t)s * 128) + lane);
        acc.x = fmaf(v.x, w, acc.x);
        acc.y = fmaf(v.y, w, acc.y);
        acc.z = fmaf(v.z, w, acc.z);
        acc.w = fmaf(v.w, w, acc.w);
    }
    acc.x = tanhf(acc.x); acc.y = tanhf(acc.y);
    acc.z = tanhf(acc.z); acc.w = tanhf(acc.w);
    *(float4*)&g_xc[(size_t)node * XC_STRIDE + outOff + lane * 4] = acc;
}

// ------------------------- layer 4 (EMB -> 1) -------------------------------
__global__ void k_layer4_dot(const float* __restrict__ W4) {
    int warp = (blockIdx.x * blockDim.x + threadIdx.x) >> 5;
    int lane = threadIdx.x & 31;
    if (warp >= N_NODES) return;
    const float* xr = g_xc + (size_t)warp * XC_STRIDE + 256;
    float4 v = *(const float4*)(xr + lane * 4);
    float4 w = *(const float4*)(W4 + lane * 4);
    float p = v.x * w.x + v.y * w.y + v.z * w.z + v.w * w.w;
#pragma unroll
    for (int off = 16; off; off >>= 1) p += __shfl_down_sync(0xffffffffu, p, off);
    if (lane == 0) g_h4[warp] = p;
}

__global__ void k_agg4(const float* __restrict__ b4) {
    int i = blockIdx.x * blockDim.x + threadIdx.x;
    if (i >= N_NODES) return;
    float acc = fmaf(g_h4[i], g_selfnorm[i], b4[0]);
    int e0 = g_rowstart[i], e1 = g_rowstart[i + 1];
    for (int e = e0; e < e1; ++e)
        acc = fmaf(g_ws[e], __ldg(&g_h4[g_srcs[e]]), acc);
    float t = tanhf(acc);
    g_xc[(size_t)i * XC_STRIDE + 384] = t;
    g_score[i] = t;
}

// ------------------------- graph bounds -------------------------------------
__global__ void k_bounds(const int* __restrict__ batch) {
    int g = threadIdx.x;
    if (g > GG) return;
    if (g == GG) { g_starts[GG] = N_NODES; return; }
    int lo = 0, hi = N_NODES;
    while (lo < hi) {
        int mid = (lo + hi) >> 1;
        if (batch[mid] < g) lo = mid + 1; else hi = mid;
    }
    g_starts[g] = lo;
}

// ------------------------- top-64 per graph ---------------------------------
__global__ __launch_bounds__(1024) void k_topk() {
    int g = blockIdx.x;
    int s = g_starts[g], e = g_starts[g + 1];
    int tid = threadIdx.x;
    __shared__ float sv[32];
    __shared__ int   si[32];

    for (int k = 0; k < SORTK; ++k) {
        float best = -1e30f;
        int bi = -1;
        for (int i = s + tid; i < e; i += 1024) {
            float v = g_score[i];
            if (v > -1e9f && (v > best || (v == best && i < bi))) { best = v; bi = i; }
        }
#pragma unroll
        for (int off = 16; off; off >>= 1) {
            float ov = __shfl_down_sync(0xffffffffu, best, off);
            int   oi = __shfl_down_sync(0xffffffffu, bi, off);
            bool take = (oi != -1) && (bi == -1 || ov > best || (ov == best && oi < bi));
            if (take) { best = ov; bi = oi; }
        }
        int lane = tid & 31, wid = tid >> 5;
        if (lane == 0) { sv[wid] = best; si[wid] = bi; }
        __syncthreads();
        if (wid == 0) {
            best = sv[lane]; bi = si[lane];
#pragma unroll
            for (int off = 16; off; off >>= 1) {
                float ov = __shfl_down_sync(0xffffffffu, best, off);
                int   oi = __shfl_down_sync(0xffffffffu, bi, off);
                bool take = (oi != -1) && (bi == -1 || ov > best || (ov == best && oi < bi));
                if (take) { best = ov; bi = oi; }
            }
            if (lane == 0) {
                g_topidx[g * SORTK + k] = bi;
                if (bi >= 0) g_score[bi] = -1e30f;
            }
        }
        __syncthreads();
    }
}

// ------------------------- pooled gather ------------------------------------
__global__ void k_pool_gather() {
    int gt = blockIdx.x;
    int idx = g_topidx[gt];
    float* outp = g_pooled + (size_t)gt * DCAT;
    if (idx >= 0) {
        const float* inp = g_xc + (size_t)idx * XC_STRIDE;
        for (int c = threadIdx.x; c < DCAT; c += blockDim.x) outp[c] = inp[c];
    } else {
        for (int c = threadIdx.x; c < DCAT; c += blockDim.x) outp[c] = 0.0f;
    }
}

// ------------------------- conv5 --------------------------------------------
__global__ void k_conv5(const float* __restrict__ cw5, const float* __restrict__ cb5) {
    int gt = blockIdx.x;
    int g = gt >> 6, t = gt & 63;
    __shared__ float row[DCAT];
    const float* pr = g_pooled + (size_t)gt * DCAT;
    for (int c = threadIdx.x; c < DCAT; c += 64) row[c] = pr[c];
    __syncthreads();
    int oc = threadIdx.x;
    float acc = cb5[oc];
    const float* w = cw5 + oc * DCAT;
    for (int j = 0; j < DCAT; ++j) acc = fmaf(w[j], row[j], acc);
    g_h5[(g * 64 + oc) * 64 + t] = fmaxf(acc, 0.0f);
}

// ------------------------- maxpool ------------------------------------------
__global__ void k_maxpool() {
    int i = blockIdx.x * blockDim.x + threadIdx.x;
    if (i >= GG * 64 * 32) return;
    g_mp[i] = fmaxf(g_h5[2 * i], g_h5[2 * i + 1]);
}

// ------------------------- conv6 --------------------------------------------
__global__ void k_conv6(const float* __restrict__ cw6, const float* __restrict__ cb6) {
    int g = blockIdx.x;
    int oc = threadIdx.x;
    __shared__ float sm[64 * 32];
    for (int i = oc; i < 64 * 32; i += 128) sm[i] = g_mp[g * 64 * 32 + i];
    __syncthreads();
    float acc[28];
    float cb = cb6[oc];
#pragma unroll
    for (int t = 0; t < 28; ++t) acc[t] = cb;
    for (int ic = 0; ic < 64; ++ic) {
#pragma unroll
        for (int kk = 0; kk < 5; ++kk) {
            float w = cw6[(oc * 64 + ic) * 5 + kk];
            const float* srow = &sm[ic * 32 + kk];
#pragma unroll
            for (int t = 0; t < 28; ++t) acc[t] = fmaf(w, srow[t], acc[t]);
        }
    }
    float* outp = g_h6 + g * 3584 + oc * 28;
#pragma unroll
    for (int t = 0; t < 28; ++t) outp[t] = fmaxf(acc[t], 0.0f);
}

// ------------------------- dense layers -------------------------------------
__inline__ __device__ float blockReduceSum(float v) {
    __shared__ float sh[32];
    int lane = threadIdx.x & 31, wid = threadIdx.x >> 5;
#pragma unroll
    for (int o = 16; o; o >>= 1) v += __shfl_down_sync(0xffffffffu, v, o);
    if (lane == 0) sh[wid] = v;
    __syncthreads();
    v = (threadIdx.x < (blockDim.x >> 5)) ? sh[lane] : 0.0f;
    if (wid == 0)
#pragma unroll
        for (int o = 16; o; o >>= 1) v += __shfl_down_sync(0xffffffffu, v, o);
    return v;
}

__global__ void k_dense1(const float* __restrict__ fw1, const float* __restrict__ fb1) {
    int j = blockIdx.x;
    const float* w = fw1 + (size_t)j * (GG * 3584);
    float s = 0.0f;
    for (int i = threadIdx.x; i < GG * 3584; i += blockDim.x) s = fmaf(g_h6[i], w[i], s);
    s = blockReduceSum(s);
    if (threadIdx.x == 0) g_out1[j] = fmaxf(s + fb1[j], 0.0f);
}

__global__ void k_dense2(const float* __restrict__ fw2, const float* __restrict__ fb2,
                         float* __restrict__ out) {
    __shared__ float so[128];
    int tid = threadIdx.x;
    so[tid] = g_out1[tid];
    __syncthreads();
    if (tid < 10) {
        float s = fb2[tid];
        const float* w = fw2 + tid * 128;
        for (int j = 0; j < 128; ++j) s = fmaf(w[j], so[j], s);
        out[tid] = s;
    }
}

// ------------------------- launch -------------------------------------------
extern "C" void kernel_launch(void* const* d_in, const int* in_sizes, int n_in,
                              void* d_out, int out_size) {
    const float* x     = (const float*)d_in[0];
    const int*   ei    = (const int*)d_in[1];
    const int*   batch = (const int*)d_in[2];
    const float* W1 = (const float*)d_in[3];  const float* b1 = (const float*)d_in[4];
    const float* W2 = (const float*)d_in[5];  const float* b2 = (const float*)d_in[6];
    const float* W3 = (const float*)d_in[7];  const float* b3 = (const float*)d_in[8];
    const float* W4 = (const float*)d_in[9];  const float* b4 = (const float*)d_in[10];
    const float* cw5 = (const float*)d_in[11]; const float* cb5 = (const float*)d_in[12];
    const float* cw6 = (const float*)d_in[13]; const float* cb6 = (const float*)d_in[14];
    const float* fw1 = (const float*)d_in[15]; const float* fb1 = (const float*)d_in[16];
    const float* fw2 = (const float*)d_in[17]; const float* fb2 = (const float*)d_in[18];
    float* out = (float*)d_out;

    const int* src = ei;
    const int* dst = ei + N_EDGES;

    const int NB_N = (N_NODES + 255) / 256;
    const int NB_E = (N_EDGES + 255) / 256;
    const int NB_GEMM = N_NODES / 128;
    const int NB_AGG  = (N_NODES * 32 + 255) / 256;   // warp per node

    // CSR build
    k_zero<<<NB_N, 256>>>();
    k_count<<<NB_E, 256>>>(src, dst);
    k_scanA<<<NBLK_SCAN, SCAN_B>>>();
    k_scanB<<<1, 32>>>();
    k_scanC<<<NBLK_SCAN, SCAN_B>>>();
    k_disnorm<<<NB_N, 256>>>();
    k_place<<<NB_E, 256>>>(src, dst);

    // layer 1 (K=100, external X)
    k_gemm<<<NB_GEMM, 256>>>(x, -1, F_IN, F_IN, W1);
    k_agg_tanh<<<NB_AGG, 256>>>(0, b1);

    // layer 2
    k_gemm<<<NB_GEMM, 256>>>(nullptr, 0, XC_STRIDE, EMB, W2);
    k_agg_tanh<<<NB_AGG, 256>>>(128, b2);

    // layer 3
    k_gemm<<<NB_GEMM, 256>>>(nullptr, 128, XC_STRIDE, EMB, W3);
    k_agg_tanh<<<NB_AGG, 256>>>(256, b3);

    // layer 4
    k_layer4_dot<<<NB_AGG, 256>>>(W4);
    k_agg4<<<NB_N, 256>>>(b4);

    // sort pooling
    k_bounds<<<1, 32>>>(batch);
    k_topk<<<GG, 1024>>>();
    k_pool_gather<<<GG * SORTK, 128>>>();

    // conv head
    k_conv5<<<GG * SORTK, 64>>>(cw5, cb5);
    k_maxpool<<<(GG * 64 * 32 + 255) / 256, 256>>>();
    k_conv6<<<GG, 128>>>(cw6, cb6);

    // dense head
    k_dense1<<<128, 256>>>(fw1, fb1);
    k_dense2<<<1, 128>>>(fw2, fb2, out);
}